// round 13
// baseline (speedup 1.0000x reference)
#include <cuda_runtime.h>
#include <cstdint>
#include <cstddef>

// ---------------------------------------------------------------------------
// DataDependentRBFKernel — three-stage pipeline (+2 no-op launches so the
// fixed ncu capture slot (-s 5 -c 1, launch #6 == #1 mod 5) lands on
// sigma_l1, the kernel we have never profiled).
//   sigma_l1:   layer-1 GEMM (8192x32x256) + gelu -> g_h1.
//               8 rows/warp, 32 rows / 128-thread block, grid 256,
//               66 KB smem -> 3 blocks/SM.
//   sigma_tail: layers 2-3 + sigmoid + affine + mu fold -> g_coef.
//   rbf_kernel: proven shape: 8 rows x 1024 z, 4 pts/thread, grid (2,1024).
// ---------------------------------------------------------------------------

#define EDIM 256
#define H1DIM 32
#define H2DIM 16

__device__ float  g_h1[8192 * H1DIM];   // layer-1 activations (1 MB)
__device__ float4 g_coef[8192];         // per-row (sc, c0, c1, cc)

__device__ __forceinline__ float ex2_approx(float x) {
    float y;
    asm("ex2.approx.f32 %0, %1;" : "=f"(y) : "f"(x));
    return y;
}
__device__ __forceinline__ float gelu_exact(float x) {
    return 0.5f * x * (1.0f + erff(x * 0.70710678118654752440f));
}

// -------------------- sigma layer 1: 32 rows / 128-thread block ------------
// warp w -> rows 8w..8w+7, lane = output unit j. Per 4-k-step:
// 4 w-LDS + 8 e-LDS.128(broadcast) + 32 FMA  (32 warp-MACs / 12 wavefronts).
__global__ __launch_bounds__(128)
void sigma_l1(const float* __restrict__ emb,
              const float* __restrict__ w1, const float* __restrict__ b1)
{
    __shared__ float e_s[32 * EDIM];        // 32 KB
    __shared__ float w1_s[EDIM * H1DIM];    // 32 KB  [k][j], j contiguous

    const int tid = threadIdx.x;
    const int rowbase = blockIdx.x * 32;

    // stage e (2048 f4) + w1 (2048 f4), 16 each per thread
    {
        const float4* e4 = reinterpret_cast<const float4*>(emb + (size_t)rowbase * EDIM);
        float4* es4 = reinterpret_cast<float4*>(e_s);
        const float4* w14 = reinterpret_cast<const float4*>(w1);
        float4* w1s4 = reinterpret_cast<float4*>(w1_s);
        #pragma unroll
        for (int i = 0; i < 16; ++i) {
            es4[tid + i * 128]  = e4[tid + i * 128];
            w1s4[tid + i * 128] = w14[tid + i * 128];
        }
    }
    __syncthreads();

    const int j = tid & 31;
    const int w = tid >> 5;                 // 0..3 -> rows 8w..8w+7
    const float* e0 = e_s + (w * 8) * EDIM;

    float acc[8];
    const float bj = __ldg(&b1[j]);
    #pragma unroll
    for (int r = 0; r < 8; ++r) acc[r] = bj;

    #pragma unroll 4
    for (int k = 0; k < EDIM; k += 4) {
        const float wv0 = w1_s[(k + 0) * H1DIM + j];
        const float wv1 = w1_s[(k + 1) * H1DIM + j];
        const float wv2 = w1_s[(k + 2) * H1DIM + j];
        const float wv3 = w1_s[(k + 3) * H1DIM + j];
        #pragma unroll
        for (int r = 0; r < 8; ++r) {
            const float4 e = *reinterpret_cast<const float4*>(e0 + r * EDIM + k);
            acc[r] = fmaf(e.x, wv0, acc[r]);
            acc[r] = fmaf(e.y, wv1, acc[r]);
            acc[r] = fmaf(e.z, wv2, acc[r]);
            acc[r] = fmaf(e.w, wv3, acc[r]);
        }
    }

    float* ho = g_h1 + (size_t)(rowbase + w * 8) * H1DIM + j;
    #pragma unroll
    for (int r = 0; r < 8; ++r)
        ho[r * H1DIM] = gelu_exact(acc[r]);     // lane j -> coalesced per warp
}

// -------------------- sigma tail: layers 2-3, 64 rows / 256 threads --------
__global__ __launch_bounds__(256)
void sigma_tail(const float* __restrict__ mu,
                const float* __restrict__ w2, const float* __restrict__ b2,
                const float* __restrict__ w3, const float* __restrict__ b3)
{
    __shared__ float w2_s[H1DIM * H2DIM];   // 2 KB
    __shared__ float h2_s[64 * H2DIM];      // 4 KB

    const int tid = threadIdx.x;
    const int rowbase = blockIdx.x * 64;

    if (tid < (H1DIM * H2DIM / 4))
        reinterpret_cast<float4*>(w2_s)[tid] =
            reinterpret_cast<const float4*>(w2)[tid];
    __syncthreads();

    // layer 2: 64 rows x 16 units = 1024 items, 4 per thread
    #pragma unroll
    for (int it = 0; it < 4; ++it) {
        const int item = tid + it * 256;
        const int r = item >> 4;
        const int m = item & 15;
        const float* h1r = g_h1 + (size_t)(rowbase + r) * H1DIM;
        float acc = __ldg(&b2[m]);
        #pragma unroll
        for (int jj = 0; jj < H1DIM; ++jj)
            acc = fmaf(__ldg(&h1r[jj]), w2_s[jj * H2DIM + m], acc);
        h2_s[r * H2DIM + m] = gelu_exact(acc);
    }
    __syncthreads();

    // layer 3 + sigmoid + affine + fold mu -> g_coef
    if (tid < 64) {
        float s = __ldg(&b3[0]);
        #pragma unroll
        for (int m = 0; m < H2DIM; ++m)
            s = fmaf(h2_s[tid * H2DIM + m], __ldg(&w3[m]), s);
        const float sig = 1.0f / (1.0f + expf(-s));
        const float sigma = 0.1f + 9.9f * sig;
        const float sc = -1.44269504088896340736f / (2.0f * sigma * sigma);
        const float2 muv = reinterpret_cast<const float2*>(mu)[rowbase + tid];
        const float c0 = -2.0f * sc * muv.x;
        const float c1 = -2.0f * sc * muv.y;
        const float cc = sc * (muv.x * muv.x + muv.y * muv.y);
        g_coef[rowbase + tid] = make_float4(sc, c0, c1, cc);
    }
}

// -------------------- RBF sweep: proven config ------------------------------
__global__ __launch_bounds__(256)
void rbf_kernel(const float* __restrict__ z, float* __restrict__ out, int M)
{
    constexpr int TILE_R = 8;

    const int t = threadIdx.x;
    const int zb = blockIdx.x * 1024 + t * 4;
    const int rowbase = blockIdx.y * TILE_R;

    float z0[4], z1[4], r2[4];
    {
        const float4* z4 = reinterpret_cast<const float4*>(z);
        #pragma unroll
        for (int i = 0; i < 2; ++i) {
            float4 v = __ldg(&z4[(size_t)(blockIdx.x * 512) + (size_t)t * 2 + i]);
            z0[2 * i]     = v.x;  z1[2 * i]     = v.y;
            z0[2 * i + 1] = v.z;  z1[2 * i + 1] = v.w;
        }
        #pragma unroll
        for (int i = 0; i < 4; ++i)
            r2[i] = z0[i] * z0[i] + z1[i] * z1[i];
    }

    float* optr = out + (size_t)rowbase * (size_t)M + (size_t)zb;

    #pragma unroll
    for (int r = 0; r < TILE_R; ++r) {
        const float4 c = __ldg(&g_coef[rowbase + r]);   // uniform -> broadcast
        float o[4];
        #pragma unroll
        for (int i = 0; i < 4; ++i) {
            float a = fmaf(c.x, r2[i], fmaf(c.y, z0[i], fmaf(c.z, z1[i], c.w)));
            o[i] = ex2_approx(a);
        }
        *reinterpret_cast<float4*>(optr) = make_float4(o[0], o[1], o[2], o[3]);
        optr += M;
    }
}

// -------------------- launch-count padding (profiling alignment) -----------
__global__ void dummy_kernel() {}

// ---------------------------------------------------------------------------
extern "C" void kernel_launch(void* const* d_in, const int* in_sizes, int n_in,
                              void* d_out, int out_size)
{
    const float* z   = (const float*)d_in[0];   // [M, 2]
    const float* mu  = (const float*)d_in[1];   // [B, N, 2]
    const float* emb = (const float*)d_in[2];   // [B, N, 256]
    const float* w1  = (const float*)d_in[3];   // [256, 32]
    const float* b1  = (const float*)d_in[4];   // [32]
    const float* w2  = (const float*)d_in[5];   // [32, 16]
    const float* b2  = (const float*)d_in[6];   // [16]
    const float* w3  = (const float*)d_in[7];   // [16, 1]
    const float* b3  = (const float*)d_in[8];   // [1]
    float* out = (float*)d_out;

    const int M  = in_sizes[0] / 2;   // 2048
    const int BN = in_sizes[1] / 2;   // 8192

    sigma_l1<<<BN / 32, 128>>>(emb, w1, b1);
    sigma_tail<<<BN / 64, 256>>>(mu, w2, b2, w3, b3);

    dim3 grid(M / 1024, BN / 8);
    rbf_kernel<<<grid, 256>>>(z, out, M);

    // two no-op launches: 5 launches/replay => ncu's skip-5 capture slot
    // (launch #6) falls on sigma_l1 of the next replay.
    dummy_kernel<<<1, 32>>>();
    dummy_kernel<<<1, 32>>>();
}